// round 8
// baseline (speedup 1.0000x reference)
#include <cuda_runtime.h>
#include <cstdint>

#define NBINS   8192
#define BDIM    4          // batch (fixed for this problem)
#define RMAX    7
#define NC      36         // chunks per batch image -> hist grid = 4*36 = 144
#define THREADS 1024
#define SEGS    8          // tail: merge segments per (r,b)
#define STHR    512        // tail block size
typedef unsigned long long u64;

// Scratch (static device globals: allocation-free rule)
__device__ int    g_part16[BDIM * NC * RMAX * (NBINS / 2)]; // packed int16 pairs
__device__ int    g_merged[RMAX * BDIM * NBINS];
__device__ int    g_cnt[BDIM * NC * RMAX];
__device__ double g_pnum[RMAX * BDIM];
__device__ int    g_pden[RMAX * BDIM];
__device__ int    g_ticketM = 0;                            // merge-phase ticket
__device__ int    g_ticket  = 0;                            // finalize ticket

__device__ __forceinline__ int binf(float x) {
    int k = __float2int_rz(x * (float)NBINS);
    return min(max(k, 0), NBINS - 1);
}

// One CTA: one chunk of one image; builds P and G u64 histograms whose six
// 10-bit fields hold per-ROI counts (masks are exact 0/1 ints -> shift-add).
// 2 shared u64 atomics per voxel instead of 2*RG u32 atomics.
template <int RG>   // ROIs in this group, 1..6
__global__ void __launch_bounds__(THREADS, 1)
hist_kernel(const float* __restrict__ pred,
            const float* __restrict__ tgt,
            const int*   __restrict__ mask,   // bool serialized as int32, [R,B,V]
            int V, int CH, int rbase, int R)
{
    extern __shared__ u64 hsh[];              // hp[NBINS] then hg[NBINS]
    u64* hp = hsh;
    u64* hg = hsh + NBINS;
    __shared__ int scnt[RG];

    const int t = threadIdx.x;
    #pragma unroll
    for (int j = t; j < 2 * NBINS; j += THREADS) hsh[j] = 0ull;
    if (t < RG) scnt[t] = 0;

    const int cid = blockIdx.x;
    const int b   = cid & (BDIM - 1);
    const int c   = cid >> 2;
    const size_t rstride = (size_t)BDIM * (size_t)V;

    const float* pp = pred + (size_t)b * V;
    const float* gp = tgt  + (size_t)b * V;
    const int*   mp = mask + ((size_t)rbase * BDIM + b) * V;

    const int start = c * CH;
    const int end   = min(V, start + CH);

    u64 cntAcc = 0ull;                        // per-thread per-ROI counts (fields)
    __syncthreads();

    for (int off = start + t * 4; off < end; off += THREADS * 4) {
        float4 pv = __ldcs(reinterpret_cast<const float4*>(pp + off));
        float4 gv = __ldcs(reinterpret_cast<const float4*>(gp + off));
        int4 mv[RG];
        #pragma unroll
        for (int r = 0; r < RG; r++)
            mv[r] = __ldcs(reinterpret_cast<const int4*>(mp + r * rstride + off));

        int p0 = binf(pv.x), p1 = binf(pv.y), p2 = binf(pv.z), p3 = binf(pv.w);
        int q0 = binf(gv.x), q1 = binf(gv.y), q2 = binf(gv.z), q3 = binf(gv.w);

        unsigned lo, hi;
        u64 inc;
        #define DO_ELEM(E, PB, QB)                                              \
        {                                                                       \
            lo = 0u; hi = 0u;                                                   \
            _Pragma("unroll")                                                   \
            for (int r = 0; r < RG; r++) {                                      \
                if (r < 3) lo += (unsigned)mv[r].E << (10 * r);                 \
                else       hi += (unsigned)mv[r].E << (10 * (r - 3));           \
            }                                                                   \
            inc = (u64)lo + ((u64)hi << 30);                                    \
            if (inc) {                                                          \
                atomicAdd(&hp[PB], inc);                                        \
                atomicAdd(&hg[QB], inc);                                        \
                cntAcc += inc;                                                  \
            }                                                                   \
        }
        DO_ELEM(x, p0, q0)
        DO_ELEM(y, p1, q1)
        DO_ELEM(z, p2, q2)
        DO_ELEM(w, p3, q3)
        #undef DO_ELEM
    }
    __syncthreads();

    // flush: per ROI-field signed diff (P - G), packed as int16 bin pairs
    #pragma unroll
    for (int j = t; j < RG * (NBINS / 2); j += THREADS) {
        int rg = j / (NBINS / 2);
        int pi = j - rg * (NBINS / 2);
        int s  = 10 * rg;
        int d0 = (int)((hp[2 * pi]     >> s) & 1023u) - (int)((hg[2 * pi]     >> s) & 1023u);
        int d1 = (int)((hp[2 * pi + 1] >> s) & 1023u) - (int)((hg[2 * pi + 1] >> s) & 1023u);
        g_part16[(size_t)cid * (R * (NBINS / 2)) + (size_t)(rbase + rg) * (NBINS / 2) + pi]
            = (d0 & 0xFFFF) | (d1 << 16);
    }

    // per-ROI masked counts: extract fields (<=32 each), exact warp reduce
    #pragma unroll
    for (int r = 0; r < RG; r++) {
        int v = (int)((cntAcc >> (10 * r)) & 1023u);
        #pragma unroll
        for (int d = 16; d; d >>= 1) v += __shfl_down_sync(0xffffffffu, v, d);
        if ((t & 31) == 0 && v) atomicAdd(&scnt[r], v);
    }
    __syncthreads();
    if (t < RG) g_cnt[cid * R + rbase + t] = scnt[t];
}

// Single tail launch, grid = RB*SEGS, 512 thr.
// Phase 1 (all CTAs): merge one 1024-bin slice of one (r,b) across NC partials.
// Phase 2 (seg==0 CTAs, after ticket spin): prefix-scan 8192 bins, sum |cum|,
// last-arriving scanner finalizes d_out.
__global__ void __launch_bounds__(STHR, 2)
tail_kernel(float* __restrict__ outp, int R, int RB, int NT)
{
    __shared__ int wsum[17];
    __shared__ long long wacc[16];
    __shared__ int sden;

    const int g   = blockIdx.x;
    const int rb  = g / SEGS;
    const int seg = g - rb * SEGS;
    const int b   = rb & 3;
    const int r   = rb >> 2;
    const int t   = threadIdx.x, lane = t & 31, w = t >> 5;
    const int PACKR = R * (NBINS / 2);

    // ---- phase 1: merge slice [seg*1024, seg*1024+1024) of (r,b) ----
    {
        const int pi = seg * (NBINS / (2 * SEGS)) + t;   // 512 packed ints/slice
        const int* base = g_part16 + r * (NBINS / 2) + pi;
        int s0 = 0, s1 = 0;
        #pragma unroll 6
        for (int c = 0; c < NC; c++) {
            int v = base[(size_t)(c * BDIM + b) * PACKR];
            s0 += (int)(short)v;
            s1 += v >> 16;
        }
        *reinterpret_cast<int2*>(g_merged + (size_t)rb * NBINS + 2 * pi) = make_int2(s0, s1);
    }
    __threadfence();
    __syncthreads();
    if (t == 0) {
        atomicAdd(&g_ticketM, 1);
        sden = 0;
        wsum[0] = 0;
    }
    if (seg != 0) return;                     // merge-only CTAs exit

    // ---- phase 2: wait for all merge slices ----
    if (t == 0) {
        while (atomicAdd(&g_ticketM, 0) < NT) { }
    }
    __syncthreads();
    __threadfence();

    // thread t owns bins [16t, 16t+16)
    const int4* m4 = reinterpret_cast<const int4*>(g_merged + (size_t)rb * NBINS + t * 16);
    int4 v0 = m4[0], v1 = m4[1], v2 = m4[2], v3 = m4[3];
    int local = v0.x + v0.y + v0.z + v0.w + v1.x + v1.y + v1.z + v1.w
              + v2.x + v2.y + v2.z + v2.w + v3.x + v3.y + v3.z + v3.w;

    int x = local;                            // warp inclusive scan
    #pragma unroll
    for (int d = 1; d < 32; d <<= 1) {
        int y = __shfl_up_sync(0xffffffffu, x, d);
        if (lane >= d) x += y;
    }
    if (lane == 31) wsum[w + 1] = x;
    __syncthreads();
    if (t == 0)
        for (int i = 1; i < 16; i++) wsum[i + 1] += wsum[i];
    __syncthreads();

    int cum = wsum[w] + x - local;            // exclusive prefix for this thread
    int acc = 0;
    #define STEP(V) cum += (V); acc += cum < 0 ? -cum : cum;
    STEP(v0.x) STEP(v0.y) STEP(v0.z) STEP(v0.w)
    STEP(v1.x) STEP(v1.y) STEP(v1.z) STEP(v1.w)
    STEP(v2.x) STEP(v2.y) STEP(v2.z) STEP(v2.w)
    STEP(v3.x) STEP(v3.y) STEP(v3.z) STEP(v3.w)
    #undef STEP

    long long a = acc;
    #pragma unroll
    for (int d = 16; d; d >>= 1) a += __shfl_down_sync(0xffffffffu, a, d);
    if (lane == 0) wacc[w] = a;

    if (t < NC) atomicAdd(&sden, g_cnt[(t * BDIM + b) * R + r]);
    __syncthreads();

    if (t == 0) {
        long long s = 0;
        #pragma unroll
        for (int i = 0; i < 16; i++) s += wacc[i];
        g_pnum[rb] = (double)s * (52.0 / (double)NBINS);
        g_pden[rb] = sden;
        __threadfence();

        int old = atomicAdd(&g_ticket, 1);
        if (old == RB - 1) {                  // last scanner: finalize
            g_ticket  = 0;                    // self-reset for graph replays
            g_ticketM = 0;
            __threadfence();
            volatile double* vn = g_pnum;
            volatile int*    vd = g_pden;
            double ls = 0.0;
            int cv = 0;
            for (int bb = 0; bb < BDIM; bb++) {
                double num = 0.0; long long dn = 0;
                for (int rr = 0; rr < RB / BDIM; rr++) {
                    num += vn[rr * BDIM + bb];
                    dn  += vd[rr * BDIM + bb];
                }
                if (dn > 0) {
                    ls += num / (double)(dn < 1 ? 1 : dn);
                    cv++;
                }
            }
            outp[0] = (float)(ls / (double)(cv > 0 ? cv : 1));
        }
    }
}

template <int RG>
static void launch_hist(const float* p, const float* g, const int* m,
                        int V, int CH, int rbase, int R)
{
    int smem = 2 * NBINS * 8;                 // 128 KB: hp + hg (u64)
    cudaFuncSetAttribute(hist_kernel<RG>, cudaFuncAttributeMaxDynamicSharedMemorySize, smem);
    hist_kernel<RG><<<BDIM * NC, THREADS, smem>>>(p, g, m, V, CH, rbase, R);
}

extern "C" void kernel_launch(void* const* d_in, const int* in_sizes, int n_in,
                              void* d_out, int out_size)
{
    const float* pred = (const float*)d_in[0];
    const float* tgt  = (const float*)d_in[1];
    const int*   mask = (const int*)d_in[2];

    int BV = in_sizes[0];                     // B*V = 4194304
    int V  = BV / BDIM;                       // 1048576
    int R  = in_sizes[2] / BV;                // 6
    int RB = R * BDIM;                        // 24
    int CH = ((V + NC - 1) / NC + 3) & ~3;    // chunk, multiple of 4

    for (int rbase = 0; rbase < R; rbase += 6) {
        int rg = R - rbase; if (rg > 6) rg = 6;
        switch (rg) {
            case 1: launch_hist<1>(pred, tgt, mask, V, CH, rbase, R); break;
            case 2: launch_hist<2>(pred, tgt, mask, V, CH, rbase, R); break;
            case 3: launch_hist<3>(pred, tgt, mask, V, CH, rbase, R); break;
            case 4: launch_hist<4>(pred, tgt, mask, V, CH, rbase, R); break;
            case 5: launch_hist<5>(pred, tgt, mask, V, CH, rbase, R); break;
            default:
            case 6: launch_hist<6>(pred, tgt, mask, V, CH, rbase, R); break;
        }
    }
    tail_kernel<<<RB * SEGS, STHR>>>((float*)d_out, R, RB, RB * SEGS);
}

// round 10
// speedup vs baseline: 1.0428x; 1.0428x over previous
#include <cuda_runtime.h>
#include <cstdint>

#define NBINS   8192
#define HALF    (NBINS / 2)
#define BDIM    4          // batch (fixed for this problem)
#define RMAX    7
#define NC      36         // chunks per batch image -> grid = 4*36 = 144 CTAs
#define THREADS 1024

// Scratch (static device globals: allocation-free rule)
__device__ int    g_part16[BDIM * NC * RMAX * HALF];  // packed int16 pairs
__device__ int    g_merged[RMAX * BDIM * NBINS];
__device__ int    g_cnt[BDIM * NC * RMAX];
__device__ double g_pnum[RMAX * BDIM];
__device__ int    g_pden[RMAX * BDIM];
__device__ int    g_bar1 = 0;                         // grid barrier 1 (self-reset)
__device__ int    g_bar2 = 0;                         // grid barrier 2 (self-reset)
__device__ int    g_ticket = 0;                       // finalize ticket (self-reset)

__device__ __forceinline__ int binf(float x) {
    int k = __float2int_rz(x * (float)NBINS);
    return min(max(k, 0), NBINS - 1);
}

// Persistent fused kernel: hist -> barrier -> merge -> barrier -> scan+finalize.
// 1 CTA/SM (big smem) and grid <= 148 => all CTAs co-resident => spin-safe.
template <int RR>
__global__ void __launch_bounds__(THREADS, 1)
fused_kernel(const float* __restrict__ pred,
             const float* __restrict__ tgt,
             const int*   __restrict__ mask,  // bool serialized as int32, [R,B,V]
             float* __restrict__ outp,
             int V, int CH, int RB, int NB)
{
    extern __shared__ int sh[];               // RR * NBINS signed counters
    __shared__ int scnt[RR];
    __shared__ int wsum[33];
    __shared__ long long wacc[32];
    __shared__ int sden;

    const int t   = threadIdx.x;
    const int cid = blockIdx.x;
    const int PACKR = RR * HALF;

    // ================= Phase A: histogram (R4-proven body) =================
    #pragma unroll
    for (int j = t; j < RR * NBINS; j += THREADS) sh[j] = 0;

    {
        const int b = cid & (BDIM - 1);
        const int c = cid >> 2;
        const size_t rstride = (size_t)BDIM * (size_t)V;

        const float* pp = pred + (size_t)b * V;
        const float* gp = tgt  + (size_t)b * V;
        const int*   mp = mask + (size_t)b * V;

        const int start = c * CH;
        const int end   = min(V, start + CH);

        int cnt[RR];
        #pragma unroll
        for (int r = 0; r < RR; r++) cnt[r] = 0;
        __syncthreads();

        for (int off = start + t * 4; off < end; off += THREADS * 4) {
            float4 pv = __ldcs(reinterpret_cast<const float4*>(pp + off));
            float4 gv = __ldcs(reinterpret_cast<const float4*>(gp + off));
            int4 mv[RR];
            #pragma unroll
            for (int r = 0; r < RR; r++)
                mv[r] = __ldcs(reinterpret_cast<const int4*>(mp + r * rstride + off));

            int p0 = binf(pv.x), p1 = binf(pv.y), p2 = binf(pv.z), p3 = binf(pv.w);
            int q0 = binf(gv.x), q1 = binf(gv.y), q2 = binf(gv.z), q3 = binf(gv.w);

            #pragma unroll
            for (int r = 0; r < RR; r++) {
                int* h = sh + r * NBINS;
                if (mv[r].x) { atomicAdd(h + p0, 1); atomicAdd(h + q0, -1); cnt[r]++; }
                if (mv[r].y) { atomicAdd(h + p1, 1); atomicAdd(h + q1, -1); cnt[r]++; }
                if (mv[r].z) { atomicAdd(h + p2, 1); atomicAdd(h + q2, -1); cnt[r]++; }
                if (mv[r].w) { atomicAdd(h + p3, 1); atomicAdd(h + q3, -1); cnt[r]++; }
            }
        }
        __syncthreads();
        if (t < RR) scnt[t] = 0;

        // flush: pack bin pairs (per-chunk counts provably fit int16)
        int* out = g_part16 + (size_t)cid * PACKR;
        #pragma unroll
        for (int j = t; j < PACKR; j += THREADS)
            out[j] = (sh[2 * j] & 0xFFFF) | (sh[2 * j + 1] << 16);
        __syncthreads();

        #pragma unroll
        for (int r = 0; r < RR; r++) {
            int v = cnt[r];
            #pragma unroll
            for (int d = 16; d; d >>= 1) v += __shfl_down_sync(0xffffffffu, v, d);
            if ((t & 31) == 0 && v) atomicAdd(&scnt[r], v);
        }
        __syncthreads();
        if (t < RR) g_cnt[cid * RR + t] = scnt[t];
    }

    // ---- grid barrier 1 (release partials, wait for all CTAs) ----
    __threadfence();
    __syncthreads();
    if (t == 0) {
        atomicAdd(&g_bar1, 1);
        while (*(volatile int*)&g_bar1 < NB) { }
    }
    __syncthreads();
    __threadfence();

    // ================= Phase B: merge across all CTAs =================
    // column idx = rb*HALF + pi; each thread sums NC chunk partials.
    {
        const int total = RB * HALF;
        for (int idx = cid * THREADS + t; idx < total; idx += NB * THREADS) {
            int rb = idx / HALF;
            int pi = idx - rb * HALF;
            int r  = rb >> 2;
            int b  = rb & 3;
            const int* base = g_part16 + (size_t)b * PACKR + r * HALF + pi;
            int s0 = 0, s1 = 0;
            #pragma unroll 6
            for (int c = 0; c < NC; c++) {
                int v = base[(size_t)c * (BDIM * PACKR)];
                s0 += (int)(short)v;
                s1 += v >> 16;
            }
            *reinterpret_cast<int2*>(g_merged + (size_t)rb * NBINS + 2 * pi)
                = make_int2(s0, s1);
        }
    }

    // ---- grid barrier 2 ----
    __threadfence();
    __syncthreads();
    if (t == 0) atomicAdd(&g_bar2, 1);
    if (cid >= RB) return;                    // merge-only CTAs done
    if (t == 0) {
        while (*(volatile int*)&g_bar2 < NB) { }
    }
    __syncthreads();
    __threadfence();

    // ================= Phase C: scan (24 CTAs) + finalize =================
    {
        const int rb = cid;
        const int b  = rb & 3;
        const int r  = rb >> 2;
        const int lane = t & 31, w = t >> 5;

        const int4* m4 = reinterpret_cast<const int4*>(g_merged + (size_t)rb * NBINS + t * 8);
        int4 v0 = m4[0], v1 = m4[1];
        int local = v0.x + v0.y + v0.z + v0.w + v1.x + v1.y + v1.z + v1.w;

        int x = local;                        // warp inclusive scan
        #pragma unroll
        for (int d = 1; d < 32; d <<= 1) {
            int y = __shfl_up_sync(0xffffffffu, x, d);
            if (lane >= d) x += y;
        }
        if (lane == 31) wsum[w + 1] = x;
        if (t == 0) { sden = 0; wsum[0] = 0; }
        __syncthreads();
        if (t == 0)
            for (int i = 1; i < 32; i++) wsum[i + 1] += wsum[i];
        __syncthreads();

        int cum = wsum[w] + x - local;        // exclusive prefix for this thread
        int acc = 0;
        #define STEP(V) cum += (V); acc += cum < 0 ? -cum : cum;
        STEP(v0.x) STEP(v0.y) STEP(v0.z) STEP(v0.w)
        STEP(v1.x) STEP(v1.y) STEP(v1.z) STEP(v1.w)
        #undef STEP

        long long a = acc;
        #pragma unroll
        for (int d = 16; d; d >>= 1) a += __shfl_down_sync(0xffffffffu, a, d);
        if (lane == 0) wacc[w] = a;

        if (t < NC) atomicAdd(&sden, g_cnt[(t * BDIM + b) * RR + r]);
        __syncthreads();

        if (t == 0) {
            long long s = 0;
            #pragma unroll
            for (int i = 0; i < 32; i++) s += wacc[i];
            g_pnum[rb] = (double)s * (52.0 / (double)NBINS);
            g_pden[rb] = sden;
            __threadfence();

            int old = atomicAdd(&g_ticket, 1);
            if (old == RB - 1) {              // last scanner: finalize
                g_ticket = 0;                 // self-reset for graph replays
                g_bar1   = 0;
                g_bar2   = 0;
                __threadfence();
                volatile double* vn = g_pnum;
                volatile int*    vd = g_pden;
                double ls = 0.0;
                int cv = 0;
                for (int bb = 0; bb < BDIM; bb++) {
                    double num = 0.0; long long dn = 0;
                    for (int rr = 0; rr < RB / BDIM; rr++) {
                        num += vn[rr * BDIM + bb];
                        dn  += vd[rr * BDIM + bb];
                    }
                    if (dn > 0) {
                        ls += num / (double)(dn < 1 ? 1 : dn);
                        cv++;
                    }
                }
                outp[0] = (float)(ls / (double)(cv > 0 ? cv : 1));
            }
        }
    }
}

template <int RR>
static void launch_fused(const float* p, const float* g, const int* m,
                         float* o, int V, int CH, int RB)
{
    int smem = RR * NBINS * 4;
    cudaFuncSetAttribute(fused_kernel<RR>, cudaFuncAttributeMaxDynamicSharedMemorySize, smem);
    int NB = BDIM * NC;                       // 144 <= 148 SMs: all co-resident
    fused_kernel<RR><<<NB, THREADS, smem>>>(p, g, m, o, V, CH, RB, NB);
}

extern "C" void kernel_launch(void* const* d_in, const int* in_sizes, int n_in,
                              void* d_out, int out_size)
{
    const float* pred = (const float*)d_in[0];
    const float* tgt  = (const float*)d_in[1];
    const int*   mask = (const int*)d_in[2];

    int BV = in_sizes[0];                     // B*V = 4194304
    int V  = BV / BDIM;                       // 1048576
    int R  = in_sizes[2] / BV;                // 6
    int RB = R * BDIM;                        // 24
    int CH = ((V + NC - 1) / NC + 3) & ~3;    // chunk, multiple of 4

    float* o = (float*)d_out;
    switch (R) {
        case 1: launch_fused<1>(pred, tgt, mask, o, V, CH, RB); break;
        case 2: launch_fused<2>(pred, tgt, mask, o, V, CH, RB); break;
        case 3: launch_fused<3>(pred, tgt, mask, o, V, CH, RB); break;
        case 4: launch_fused<4>(pred, tgt, mask, o, V, CH, RB); break;
        case 5: launch_fused<5>(pred, tgt, mask, o, V, CH, RB); break;
        case 7: launch_fused<7>(pred, tgt, mask, o, V, CH, RB); break;
        default:
        case 6: launch_fused<6>(pred, tgt, mask, o, V, CH, RB); break;
    }
}

// round 11
// speedup vs baseline: 1.0737x; 1.0296x over previous
#include <cuda_runtime.h>
#include <cstdint>
typedef unsigned long long u64;

#define NBINS   2048
#define HALF    (NBINS / 2)
#define BDIM    4          // batch (fixed for this problem)
#define RMAX    7
#define NC      72         // chunks per batch image -> grid = 4*72 = 288 CTAs
#define THREADS 768        // 2 CTAs/SM -> 48 warps/SM

// Scratch (static device globals: allocation-free rule)
__device__ int    g_part16[BDIM * NC * RMAX * HALF];  // packed int16 pairs
__device__ int    g_merged[RMAX * BDIM * NBINS];
__device__ int    g_cnt[BDIM * NC * RMAX];
__device__ double g_pnum[RMAX * BDIM];
__device__ int    g_pden[RMAX * BDIM];
__device__ int    g_bar1 = 0;                         // grid barrier (self-reset)
__device__ int    g_bar2 = 0;                         // grid barrier (self-reset)
__device__ int    g_ticket = 0;                       // finalize ticket (self-reset)

__device__ __forceinline__ int binf(float x) {
    int k = __float2int_rz(x * (float)NBINS);
    return min(max(k, 0), NBINS - 1);
}

// Persistent fused kernel: hist -> barrier -> merge -> barrier -> scan+finalize.
// 288 CTAs at 2/SM: all co-resident (288 <= 2*148) => spin barriers safe.
template <int RR>
__global__ void __launch_bounds__(THREADS, 2)
fused_kernel(const float* __restrict__ pred,
             const float* __restrict__ tgt,
             const int*   __restrict__ mask,  // bool serialized as int32, [R,B,V]
             float* __restrict__ outp,
             int V, int CH, int RB, int NB)
{
    extern __shared__ int sh[];               // RR * NBINS signed counters
    __shared__ int scnt[RR];
    __shared__ int wsum[17];
    __shared__ long long wacc[16];
    __shared__ int sden;

    const int t   = threadIdx.x;
    const int cid = blockIdx.x;
    const int PACKR = RR * HALF;

    // ================= Phase A: histogram =================
    #pragma unroll
    for (int j = t; j < RR * NBINS; j += THREADS) sh[j] = 0;
    if (t < RR) scnt[t] = 0;

    {
        const int b = cid & (BDIM - 1);
        const int c = cid >> 2;
        const size_t rstride = (size_t)BDIM * (size_t)V;

        const float* pp = pred + (size_t)b * V;
        const float* gp = tgt  + (size_t)b * V;
        const int*   mp = mask + (size_t)b * V;

        const int start = c * CH;
        const int end   = min(V, start + CH);

        u64 cntAcc = 0ull;                    // six 10-bit per-ROI counters
        __syncthreads();

        for (int off = start + t * 4; off < end; off += THREADS * 4) {
            float4 pv = __ldcs(reinterpret_cast<const float4*>(pp + off));
            float4 gv = __ldcs(reinterpret_cast<const float4*>(gp + off));
            int p0 = binf(pv.x), p1 = binf(pv.y), p2 = binf(pv.z), p3 = binf(pv.w);
            int q0 = binf(gv.x), q1 = binf(gv.y), q2 = binf(gv.z), q3 = binf(gv.w);

            const int* m = mp + off;
            #pragma unroll
            for (int r = 0; r < RR; r++) {
                int4 mv = __ldcs(reinterpret_cast<const int4*>(m));
                m += rstride;
                int* h = sh + r * NBINS;
                if (mv.x) { atomicAdd(h + p0, 1); atomicAdd(h + q0, -1); }
                if (mv.y) { atomicAdd(h + p1, 1); atomicAdd(h + q1, -1); }
                if (mv.z) { atomicAdd(h + p2, 1); atomicAdd(h + q2, -1); }
                if (mv.w) { atomicAdd(h + p3, 1); atomicAdd(h + q3, -1); }
                cntAcc += (u64)(unsigned)(mv.x + mv.y + mv.z + mv.w) << (10 * r);
            }
        }
        __syncthreads();

        // flush: pack bin pairs (per-chunk counts provably fit int16)
        int* out = g_part16 + (size_t)cid * PACKR;
        #pragma unroll
        for (int j = t; j < PACKR; j += THREADS)
            out[j] = (sh[2 * j] & 0xFFFF) | (sh[2 * j + 1] << 16);

        // per-ROI masked counts
        #pragma unroll
        for (int r = 0; r < RR; r++) {
            int v = (int)((cntAcc >> (10 * r)) & 1023u);
            #pragma unroll
            for (int d = 16; d; d >>= 1) v += __shfl_down_sync(0xffffffffu, v, d);
            if ((t & 31) == 0 && v) atomicAdd(&scnt[r], v);
        }
        __syncthreads();
        if (t < RR) g_cnt[cid * RR + t] = scnt[t];
    }

    // ---- grid barrier 1 ----
    __threadfence();
    __syncthreads();
    if (t == 0) {
        atomicAdd(&g_bar1, 1);
        while (*(volatile int*)&g_bar1 < NB) { }
    }
    __syncthreads();
    __threadfence();

    // ================= Phase B: merge =================
    // column idx = rb*HALF + pi; each active thread sums NC chunk partials.
    {
        const int total = RB * HALF;          // 24576 columns
        for (int idx = cid * THREADS + t; idx < total; idx += NB * THREADS) {
            int rb = idx >> 10;               // HALF == 1024
            int pi = idx & (HALF - 1);
            int r  = rb >> 2;
            int b  = rb & 3;
            const int* base = g_part16 + (size_t)b * PACKR + r * HALF + pi;
            int s0 = 0, s1 = 0;
            #pragma unroll 8
            for (int c = 0; c < NC; c++) {
                int v = base[(size_t)c * (BDIM * PACKR)];
                s0 += (int)(short)v;
                s1 += v >> 16;
            }
            *reinterpret_cast<int2*>(g_merged + (size_t)rb * NBINS + 2 * pi)
                = make_int2(s0, s1);
        }
    }

    // ---- grid barrier 2 ----
    __threadfence();
    __syncthreads();
    if (t == 0) atomicAdd(&g_bar2, 1);
    if (cid >= RB) return;                    // merge-only CTAs done
    if (t == 0) {
        while (*(volatile int*)&g_bar2 < NB) { }
    }
    __syncthreads();
    __threadfence();

    // ================= Phase C: scan (RB CTAs) + finalize =================
    {
        const int rb = cid;
        const int b  = rb & 3;
        const int r  = rb >> 2;
        const int lane = t & 31, w = t >> 5;

        // threads 0..511 own bins [4t, 4t+4)
        int4 v = make_int4(0, 0, 0, 0);
        if (t < 512)
            v = *reinterpret_cast<const int4*>(g_merged + (size_t)rb * NBINS + t * 4);
        int local = v.x + v.y + v.z + v.w;

        int x = local;                        // warp inclusive scan
        #pragma unroll
        for (int d = 1; d < 32; d <<= 1) {
            int y = __shfl_up_sync(0xffffffffu, x, d);
            if (lane >= d) x += y;
        }
        if (w < 16 && lane == 31) wsum[w + 1] = x;
        if (t == 0) { sden = 0; wsum[0] = 0; }
        __syncthreads();
        if (t == 0)
            for (int i = 1; i < 16; i++) wsum[i + 1] += wsum[i];
        __syncthreads();

        long long a = 0;
        if (t < 512) {
            int cum = wsum[w] + x - local;    // exclusive prefix for this thread
            int acc = 0;
            cum += v.x; acc += cum < 0 ? -cum : cum;
            cum += v.y; acc += cum < 0 ? -cum : cum;
            cum += v.z; acc += cum < 0 ? -cum : cum;
            cum += v.w; acc += cum < 0 ? -cum : cum;
            a = acc;
        }
        #pragma unroll
        for (int d = 16; d; d >>= 1) a += __shfl_down_sync(0xffffffffu, a, d);
        if (w < 16 && lane == 0) wacc[w] = a;

        if (t < NC) atomicAdd(&sden, g_cnt[(t * BDIM + b) * RR + r]);
        __syncthreads();

        if (t == 0) {
            long long s = 0;
            #pragma unroll
            for (int i = 0; i < 16; i++) s += wacc[i];
            g_pnum[rb] = (double)s * (52.0 / (double)NBINS);
            g_pden[rb] = sden;
            __threadfence();

            int old = atomicAdd(&g_ticket, 1);
            if (old == RB - 1) {              // last scanner: finalize
                g_ticket = 0;                 // self-reset for graph replays
                g_bar1   = 0;
                g_bar2   = 0;
                __threadfence();
                volatile double* vn = g_pnum;
                volatile int*    vd = g_pden;
                double ls = 0.0;
                int cv = 0;
                for (int bb = 0; bb < BDIM; bb++) {
                    double num = 0.0; long long dn = 0;
                    for (int rr = 0; rr < RB / BDIM; rr++) {
                        num += vn[rr * BDIM + bb];
                        dn  += vd[rr * BDIM + bb];
                    }
                    if (dn > 0) {
                        ls += num / (double)(dn < 1 ? 1 : dn);
                        cv++;
                    }
                }
                outp[0] = (float)(ls / (double)(cv > 0 ? cv : 1));
            }
        }
    }
}

template <int RR>
static void launch_fused(const float* p, const float* g, const int* m,
                         float* o, int V, int CH, int RB)
{
    int smem = RR * NBINS * 4;                // 48 KB for RR=6 -> 2 CTAs/SM
    cudaFuncSetAttribute(fused_kernel<RR>, cudaFuncAttributeMaxDynamicSharedMemorySize, smem);
    int NB = BDIM * NC;                       // 288 <= 2*148: all co-resident
    fused_kernel<RR><<<NB, THREADS, smem>>>(p, g, m, o, V, CH, RB, NB);
}

extern "C" void kernel_launch(void* const* d_in, const int* in_sizes, int n_in,
                              void* d_out, int out_size)
{
    const float* pred = (const float*)d_in[0];
    const float* tgt  = (const float*)d_in[1];
    const int*   mask = (const int*)d_in[2];

    int BV = in_sizes[0];                     // B*V = 4194304
    int V  = BV / BDIM;                       // 1048576
    int R  = in_sizes[2] / BV;                // 6
    int RB = R * BDIM;                        // 24
    int CH = ((V + NC - 1) / NC + 3) & ~3;    // chunk, multiple of 4

    float* o = (float*)d_out;
    switch (R) {
        case 1: launch_fused<1>(pred, tgt, mask, o, V, CH, RB); break;
        case 2: launch_fused<2>(pred, tgt, mask, o, V, CH, RB); break;
        case 3: launch_fused<3>(pred, tgt, mask, o, V, CH, RB); break;
        case 4: launch_fused<4>(pred, tgt, mask, o, V, CH, RB); break;
        case 5: launch_fused<5>(pred, tgt, mask, o, V, CH, RB); break;
        case 7: launch_fused<7>(pred, tgt, mask, o, V, CH, RB); break;
        default:
        case 6: launch_fused<6>(pred, tgt, mask, o, V, CH, RB); break;
    }
}